// round 4
// baseline (speedup 1.0000x reference)
#include <cuda_runtime.h>
#include <math.h>
#include <stdint.h>

// MultiHeadAttention: B=4, S=2048, E=1024, H=16, D=64
// Outputs (tuple order): out [B,S,E] fp32, attention_weights [B,H,S,S] fp32.
//
// Pipeline (exact fp32; tensor cores after first profile):
//   1) Q/K/V projections: SGEMM 128x128x16, 8x8 per thread
//   2) scores_stats: per (b,h, 128-row stripe) compute raw scores Q Kh^T/8
//      (Q resident in smem, K streamed in BK=16 chunks), write raw scores,
//      keep online row max/sum in registers via half-warp shuffles -> g_m/g_s
//   3) norm_pv: read raw scores once, normalize with (m,s), write normalized
//      attention_weights, accumulate P@V; feature-dim softmax in epilogue
//   4) out projection into d_out[0 .. M*E)

#define BB   4
#define SS   2048
#define EE   1024
#define HH   16
#define DD   64
#define MTOT (BB*SS)          // 8192
#define BH   (BB*HH)          // 64

// Scratch (static device globals -- no allocation APIs)
__device__ float g_q[MTOT*EE];
__device__ float g_k[MTOT*EE];
__device__ float g_v[MTOT*EE];
__device__ float g_ctx[MTOT*EE];
__device__ float g_m[BH*SS];
__device__ float g_s[BH*SS];

// ---------------------------------------------------------------------------
// Generic projection SGEMM: C[M,1024] = A[M,1024] @ W[1024,1024]^T + bias
// BM=BN=128, BK=16, 256 threads, 8x8 per thread.
// a_sel: 0 -> A = A_ext (input tensor), 1 -> A = g_ctx
// c_sel: 0 -> C = g_q, 1 -> C = g_k, 2 -> C = g_v, 3 -> C = C_ext (d_out)
// ---------------------------------------------------------------------------
__global__ __launch_bounds__(256) void gemm_bias_kernel(
    const float* __restrict__ A_ext, int a_sel,
    const float* __restrict__ W, const float* __restrict__ bias,
    float* __restrict__ C_ext, int c_sel)
{
    const float* __restrict__ A = (a_sel == 0) ? A_ext : g_ctx;
    float* __restrict__ C;
    switch (c_sel) {
        case 0:  C = g_q;   break;
        case 1:  C = g_k;   break;
        case 2:  C = g_v;   break;
        default: C = C_ext; break;
    }

    const int K = 1024, N = 1024;
    __shared__ __align__(16) float As[16][128];
    __shared__ __align__(16) float Bs[16][128];

    const int tid = threadIdx.x;
    const int rowBase = blockIdx.y * 128;
    const int colBase = blockIdx.x * 128;
    const int ty = tid >> 4;          // 0..15
    const int tx = tid & 15;          // 0..15

    float acc[8][8];
#pragma unroll
    for (int i = 0; i < 8; i++)
#pragma unroll
        for (int j = 0; j < 8; j++) acc[i][j] = 0.f;

    for (int k0 = 0; k0 < K; k0 += 16) {
#pragma unroll
        for (int l = 0; l < 2; l++) {
            int id = tid + l * 256;          // 0..511
            int r  = id >> 2;                // 0..127
            int c4 = (id & 3) << 2;          // 0,4,8,12
            float4 av = *(const float4*)&A[(size_t)(rowBase + r) * K + k0 + c4];
            As[c4 + 0][r] = av.x; As[c4 + 1][r] = av.y;
            As[c4 + 2][r] = av.z; As[c4 + 3][r] = av.w;
            float4 wv = *(const float4*)&W[(size_t)(colBase + r) * K + k0 + c4];
            Bs[c4 + 0][r] = wv.x; Bs[c4 + 1][r] = wv.y;
            Bs[c4 + 2][r] = wv.z; Bs[c4 + 3][r] = wv.w;
        }
        __syncthreads();
#pragma unroll
        for (int kk = 0; kk < 16; kk++) {
            float4 a0 = *(const float4*)&As[kk][ty * 8];
            float4 a1 = *(const float4*)&As[kk][ty * 8 + 4];
            float4 b0 = *(const float4*)&Bs[kk][tx * 8];
            float4 b1 = *(const float4*)&Bs[kk][tx * 8 + 4];
            float a[8] = {a0.x, a0.y, a0.z, a0.w, a1.x, a1.y, a1.z, a1.w};
            float b[8] = {b0.x, b0.y, b0.z, b0.w, b1.x, b1.y, b1.z, b1.w};
#pragma unroll
            for (int i = 0; i < 8; i++)
#pragma unroll
                for (int j = 0; j < 8; j++) acc[i][j] += a[i] * b[j];
        }
        __syncthreads();
    }

    float4 bb0 = *(const float4*)&bias[colBase + tx * 8];
    float4 bb1 = *(const float4*)&bias[colBase + tx * 8 + 4];
#pragma unroll
    for (int i = 0; i < 8; i++) {
        int row = rowBase + ty * 8 + i;
        float4 o0 = make_float4(acc[i][0] + bb0.x, acc[i][1] + bb0.y,
                                acc[i][2] + bb0.z, acc[i][3] + bb0.w);
        float4 o1 = make_float4(acc[i][4] + bb1.x, acc[i][5] + bb1.y,
                                acc[i][6] + bb1.z, acc[i][7] + bb1.w);
        *(float4*)&C[(size_t)row * N + colBase + tx * 8]     = o0;
        *(float4*)&C[(size_t)row * N + colBase + tx * 8 + 4] = o1;
    }
}

// ---------------------------------------------------------------------------
// scores + online row stats. One block = 128 query rows of one (b,h), looping
// over all 16 key tiles of 128 columns. Q tile (128x64) resident in smem;
// K streamed in [16][128] chunks (smem: 32KB + 8KB = 40KB < 48KB).
// Row stats reduced across the 16 threads of a row via half-warp butterflies;
// running (m, s) kept replicated in registers. grid = (S/128, B*H).
// ---------------------------------------------------------------------------
__global__ __launch_bounds__(256) void scores_stats_kernel(float* __restrict__ attn)
{
    const int bh = blockIdx.y;
    const int b  = bh >> 4;
    const int h  = bh & 15;
    const int rowBase = blockIdx.x * 128;
    const float* __restrict__ Qp = g_q + (size_t)b * SS * EE + h * DD;
    const float* __restrict__ Kp = g_k + (size_t)b * SS * EE + h * DD;
    float* __restrict__ Cb = attn + (size_t)bh * SS * SS;

    __shared__ __align__(16) float Qs[64][128];   // [d][row]   32 KB
    __shared__ __align__(16) float Ks[16][128];   // [d16][col]  8 KB

    const int tid = threadIdx.x;
    const int ty = tid >> 4;          // 0..15
    const int tx = tid & 15;          // 0..15

    // Load Q tile (128 rows x 64 d), transposed into [d][row]
#pragma unroll
    for (int l = 0; l < 8; l++) {
        int id = tid + l * 256;          // 0..2047 float4 slots
        int r  = id >> 4;                // 0..127
        int c4 = (id & 15) << 2;         // 0..60
        float4 qv = *(const float4*)&Qp[(size_t)(rowBase + r) * EE + c4];
        Qs[c4 + 0][r] = qv.x; Qs[c4 + 1][r] = qv.y;
        Qs[c4 + 2][r] = qv.z; Qs[c4 + 3][r] = qv.w;
    }

    float m_run[8], s_run[8];
#pragma unroll
    for (int i = 0; i < 8; i++) { m_run[i] = -INFINITY; s_run[i] = 0.f; }

    for (int ct = 0; ct < SS / 128; ct++) {
        const int colBase = ct * 128;

        float acc[8][8];
#pragma unroll
        for (int i = 0; i < 8; i++)
#pragma unroll
            for (int j = 0; j < 8; j++) acc[i][j] = 0.f;

        // K streamed in 4 chunks of 16 depth
#pragma unroll
        for (int kc = 0; kc < 4; kc++) {
            __syncthreads();
            {
                int id = tid + tid;          // dummy to keep scope clean
                (void)id;
            }
#pragma unroll
            for (int l = 0; l < 2; l++) {
                int id = tid + l * 256;      // 0..511
                int r  = id >> 2;            // 0..127 (key col)
                int c4 = (id & 3) << 2;      // 0,4,8,12
                float4 kv = *(const float4*)&Kp[(size_t)(colBase + r) * EE + kc * 16 + c4];
                Ks[c4 + 0][r] = kv.x; Ks[c4 + 1][r] = kv.y;
                Ks[c4 + 2][r] = kv.z; Ks[c4 + 3][r] = kv.w;
            }
            __syncthreads();
#pragma unroll
            for (int kk = 0; kk < 16; kk++) {
                float4 a0 = *(const float4*)&Qs[kc * 16 + kk][ty * 8];
                float4 a1 = *(const float4*)&Qs[kc * 16 + kk][ty * 8 + 4];
                float4 b0 = *(const float4*)&Ks[kk][tx * 8];
                float4 b1 = *(const float4*)&Ks[kk][tx * 8 + 4];
                float a[8] = {a0.x, a0.y, a0.z, a0.w, a1.x, a1.y, a1.z, a1.w};
                float bv[8] = {b0.x, b0.y, b0.z, b0.w, b1.x, b1.y, b1.z, b1.w};
#pragma unroll
                for (int i = 0; i < 8; i++)
#pragma unroll
                    for (int j = 0; j < 8; j++) acc[i][j] += a[i] * bv[j];
            }
        }

        // scale + write raw scores
#pragma unroll
        for (int i = 0; i < 8; i++) {
#pragma unroll
            for (int j = 0; j < 8; j++) acc[i][j] *= 0.125f;
            int row = rowBase + ty * 8 + i;
            float4 o0 = make_float4(acc[i][0], acc[i][1], acc[i][2], acc[i][3]);
            float4 o1 = make_float4(acc[i][4], acc[i][5], acc[i][6], acc[i][7]);
            *(float4*)&Cb[(size_t)row * SS + colBase + tx * 8]     = o0;
            *(float4*)&Cb[(size_t)row * SS + colBase + tx * 8 + 4] = o1;
        }

        // online stats: butterfly over the 16 lanes sharing each row
#pragma unroll
        for (int i = 0; i < 8; i++) {
            float rmax = acc[i][0];
#pragma unroll
            for (int j = 1; j < 8; j++) rmax = fmaxf(rmax, acc[i][j]);
#pragma unroll
            for (int off = 8; off > 0; off >>= 1)
                rmax = fmaxf(rmax, __shfl_xor_sync(0xffffffffu, rmax, off));
            float m_new = fmaxf(m_run[i], rmax);
            float psum = 0.f;
#pragma unroll
            for (int j = 0; j < 8; j++) psum += __expf(acc[i][j] - m_new);
#pragma unroll
            for (int off = 8; off > 0; off >>= 1)
                psum += __shfl_xor_sync(0xffffffffu, psum, off);
            s_run[i] = s_run[i] * __expf(m_run[i] - m_new) + psum;
            m_run[i] = m_new;
        }
    }

    if (tx == 0) {
#pragma unroll
        for (int i = 0; i < 8; i++) {
            int row = rowBase + ty * 8 + i;
            g_m[(size_t)bh * SS + row] = m_run[i];
            g_s[(size_t)bh * SS + row] = s_run[i];
        }
    }
}

// ---------------------------------------------------------------------------
// normalize + PV: read raw scores once, write normalized attention_weights,
// accumulate ctx = P @ V, feature-dim softmax fused into the epilogue.
// grid = (S/128, B*H), 256 threads, BM=128, BN=64, BK=16, 8x4 per thread.
// ---------------------------------------------------------------------------
__global__ __launch_bounds__(256) void norm_pv_kernel(float* __restrict__ attn)
{
    const int bh = blockIdx.y;
    const int b  = bh >> 4;
    const int h  = bh & 15;
    const int rowBase = blockIdx.x * 128;
    float* __restrict__ P = attn + (size_t)bh * SS * SS;
    const float* __restrict__ V = g_v + (size_t)b * SS * EE + h * DD;

    __shared__ __align__(16) float Ps[16][128];
    __shared__ __align__(16) float Vs[16][64];
    __shared__ float Ct[128][65];
    __shared__ float m_s[128];
    __shared__ float i_s[128];

    const int tid = threadIdx.x;
    const int ty = tid >> 4;          // 0..15
    const int tx = tid & 15;          // 0..15

    if (tid < 128) {
        m_s[tid] = g_m[(size_t)bh * SS + rowBase + tid];
        i_s[tid] = 1.f / g_s[(size_t)bh * SS + rowBase + tid];
    }
    __syncthreads();

    float acc[8][4];
#pragma unroll
    for (int i = 0; i < 8; i++)
#pragma unroll
        for (int j = 0; j < 4; j++) acc[i][j] = 0.f;

    for (int k0 = 0; k0 < SS; k0 += 16) {
#pragma unroll
        for (int l = 0; l < 2; l++) {
            int id = tid + l * 256;
            int r  = id >> 2;                // 0..127 (query row)
            int c4 = (id & 3) << 2;          // 0,4,8,12
            float* addr = &P[(size_t)(rowBase + r) * SS + k0 + c4];
            float4 pv = *(const float4*)addr;
            float m = m_s[r], inv = i_s[r];
            pv.x = __expf(pv.x - m) * inv;
            pv.y = __expf(pv.y - m) * inv;
            pv.z = __expf(pv.z - m) * inv;
            pv.w = __expf(pv.w - m) * inv;
            *(float4*)addr = pv;             // normalized attention_weights out
            Ps[c4 + 0][r] = pv.x; Ps[c4 + 1][r] = pv.y;
            Ps[c4 + 2][r] = pv.z; Ps[c4 + 3][r] = pv.w;
        }
        {
            int r = tid >> 4;               // 0..15 (k)
            int c = (tid & 15) << 2;        // 0..60
            *(float4*)&Vs[r][c] = *(const float4*)&V[(size_t)(k0 + r) * EE + c];
        }
        __syncthreads();
#pragma unroll
        for (int kk = 0; kk < 16; kk++) {
            float4 a0 = *(const float4*)&Ps[kk][ty * 8];
            float4 a1 = *(const float4*)&Ps[kk][ty * 8 + 4];
            float4 b0 = *(const float4*)&Vs[kk][tx * 4];
            float a[8] = {a0.x, a0.y, a0.z, a0.w, a1.x, a1.y, a1.z, a1.w};
            float bv[4] = {b0.x, b0.y, b0.z, b0.w};
#pragma unroll
            for (int i = 0; i < 8; i++)
#pragma unroll
                for (int j = 0; j < 4; j++) acc[i][j] += a[i] * bv[j];
        }
        __syncthreads();
    }

#pragma unroll
    for (int i = 0; i < 8; i++)
#pragma unroll
        for (int j = 0; j < 4; j++) Ct[ty * 8 + i][tx * 4 + j] = acc[i][j];
    __syncthreads();

    if (tid < 128) {
        const int r = tid;
        float m = Ct[r][0];
#pragma unroll
        for (int d = 1; d < DD; d++) m = fmaxf(m, Ct[r][d]);
        float s = 0.f;
#pragma unroll
        for (int d = 0; d < DD; d++) { float e = __expf(Ct[r][d] - m); Ct[r][d] = e; s += e; }
        float inv = 1.f / s;
        float* __restrict__ dst = g_ctx + ((size_t)b * SS + rowBase + r) * EE + h * DD;
#pragma unroll
        for (int d = 0; d < DD; d++) dst[d] = Ct[r][d] * inv;
    }
}

// ---------------------------------------------------------------------------
extern "C" void kernel_launch(void* const* d_in, const int* in_sizes, int n_in,
                              void* d_out, int out_size)
{
    const float* key   = (const float*)d_in[0];
    const float* query = (const float*)d_in[1];
    const float* value = (const float*)d_in[2];
    const float* wk_w  = (const float*)d_in[3];
    const float* wk_b  = (const float*)d_in[4];
    const float* wq_w  = (const float*)d_in[5];
    const float* wq_b  = (const float*)d_in[6];
    const float* wv_w  = (const float*)d_in[7];
    const float* wv_b  = (const float*)d_in[8];
    const float* out_w = (const float*)d_in[9];
    const float* out_b = (const float*)d_in[10];

    float* out  = (float*)d_out;                       // [B,S,E]
    float* attn = out + (size_t)MTOT * EE;             // [B,H,S,S]

    dim3 gProj(EE / 128, MTOT / 128);                  // (8, 64)
    gemm_bias_kernel<<<gProj, 256>>>(query, 0, wq_w, wq_b, nullptr, 0);
    gemm_bias_kernel<<<gProj, 256>>>(key,   0, wk_w, wk_b, nullptr, 1);
    gemm_bias_kernel<<<gProj, 256>>>(value, 0, wv_w, wv_b, nullptr, 2);

    dim3 gScores(SS / 128, BH);                        // (16, 64)
    scores_stats_kernel<<<gScores, 256>>>(attn);

    dim3 gPV(SS / 128, BH);                            // (16, 64)
    norm_pv_kernel<<<gPV, 256>>>(attn);

    gemm_bias_kernel<<<gProj, 256>>>(nullptr, 1, out_w, out_b, out, 3);
}

// round 6
// speedup vs baseline: 1.3320x; 1.3320x over previous
#include <cuda_runtime.h>
#include <cuda_bf16.h>
#include <math.h>
#include <stdint.h>

// MultiHeadAttention: B=4, S=2048, E=1024, H=16, D=64
// Outputs: out [B,S,E] fp32, attention_weights [B,H,S,S] fp32.
//
// R5: harness compiles for base sm_100 (no 'a') -> tcgen05 unavailable.
// Projection GEMMs use warp-level mma.sync m16n8k16 bf16 (sm_80 ISA, runs on
// the tensor pipe) with 2-term bf16 split (hi+lo, drop lo*lo) for ~fp32
// accuracy (~2^-18/elem). Attention kernels remain exact fp32 (R3/R4 design).

#define BB   4
#define SS   2048
#define EE   1024
#define HH   16
#define DD   64
#define MTOT (BB*SS)          // 8192
#define BH   (BB*HH)          // 64

__device__ float g_q[MTOT*EE];
__device__ float g_k[MTOT*EE];
__device__ float g_v[MTOT*EE];
__device__ float g_ctx[MTOT*EE];
__device__ float g_m[BH*SS];
__device__ float g_s[BH*SS];

// ===========================================================================
// bf16 hi/lo split helpers + warp mma
// ===========================================================================
__device__ __forceinline__ void f32x2_hilo(float x, float y, uint32_t& hi, uint32_t& lo) {
    __nv_bfloat162 h, l;
    h.x = __float2bfloat16(x); l.x = __float2bfloat16(x - __bfloat162float(h.x));
    h.y = __float2bfloat16(y); l.y = __float2bfloat16(y - __bfloat162float(h.y));
    hi = *(uint32_t*)&h; lo = *(uint32_t*)&l;
}

__device__ __forceinline__ void mma_bf16(float* d,
    uint32_t a0, uint32_t a1, uint32_t a2, uint32_t a3, uint32_t b0, uint32_t b1)
{
    asm volatile(
        "mma.sync.aligned.m16n8k16.row.col.f32.bf16.bf16.f32 "
        "{%0,%1,%2,%3}, {%4,%5,%6,%7}, {%8,%9}, {%0,%1,%2,%3};"
        : "+f"(d[0]), "+f"(d[1]), "+f"(d[2]), "+f"(d[3])
        : "r"(a0), "r"(a1), "r"(a2), "r"(a3), "r"(b0), "r"(b1));
}

// ===========================================================================
// Tensor-core projection GEMM: C[8192,1024] = A @ W^T + bias.
// CTA 128x128, K chunks of 64 bf16. 8 warps = 4(M) x 2(N); warp tile 32x64.
// Smem (dynamic, 73.7KB): Ahi/Alo [128][72] bf16, Bhi/Blo [128][72] bf16
// (72 = 64 + 8 pad -> conflict-free 32-bit fragment loads, row stride 144B).
// a_sel: 0 -> A_ext, 1 -> g_ctx.  c_sel: 0 g_q, 1 g_k, 2 g_v, 3 C_ext.
// ===========================================================================
#define TPAD   72                       // bf16 elems per smem row
#define TROWB  (TPAD*2)                 // 144 bytes
#define OFF_AHI 0
#define OFF_ALO (128*TROWB)             // 18432
#define OFF_BHI (2*128*TROWB)           // 36864
#define OFF_BLO (3*128*TROWB)           // 55296
#define GEMM_SMEM (4*128*TROWB)         // 73728

__global__ __launch_bounds__(256, 1) void gemm_mma_kernel(
    const float* __restrict__ A_ext, int a_sel,
    const float* __restrict__ W, const float* __restrict__ bias,
    float* __restrict__ C_ext, int c_sel)
{
    extern __shared__ __align__(16) char smem[];

    const float* __restrict__ A = (a_sel == 0) ? A_ext : g_ctx;
    float* __restrict__ C;
    switch (c_sel) {
        case 0:  C = g_q;   break;
        case 1:  C = g_k;   break;
        case 2:  C = g_v;   break;
        default: C = C_ext; break;
    }

    const int tid  = threadIdx.x;
    const int wid  = tid >> 5;
    const int lane = tid & 31;
    const int g    = lane >> 2;          // 0..7  (mma group)
    const int tig  = lane & 3;           // 0..3
    const int warpM = wid & 3;           // 4 M-warps (32 rows each)
    const int warpN = wid >> 2;          // 2 N-warps (64 cols each)
    const int rowBase = blockIdx.y * 128;
    const int colBase = blockIdx.x * 128;

    float acc[2][8][4];                  // [m-tile][n-tile][frag]
#pragma unroll
    for (int mt = 0; mt < 2; mt++)
#pragma unroll
        for (int nt = 0; nt < 8; nt++)
#pragma unroll
            for (int f = 0; f < 4; f++) acc[mt][nt][f] = 0.f;

    for (int kc = 0; kc < 16; kc++) {
        const int k0g = kc * 64;
        // --- stage A (rows) and W (cols) chunk as bf16 hi/lo ---
#pragma unroll
        for (int l = 0; l < 16; l++) {
            int id   = tid + l * 256;        // 0..4095
            int slot = id & 2047;            // within tensor
            int r    = slot >> 4;            // 0..127
            int c4   = (slot & 15) << 2;     // 0..60
            uint32_t so = (uint32_t)(r * TROWB + c4 * 2);
            if (id < 2048) {
                float4 v = *(const float4*)&A[(size_t)(rowBase + r) * EE + k0g + c4];
                uint32_t h0, l0, h1, l1;
                f32x2_hilo(v.x, v.y, h0, l0);
                f32x2_hilo(v.z, v.w, h1, l1);
                *(uint32_t*)(smem + OFF_AHI + so)     = h0;
                *(uint32_t*)(smem + OFF_AHI + so + 4) = h1;
                *(uint32_t*)(smem + OFF_ALO + so)     = l0;
                *(uint32_t*)(smem + OFF_ALO + so + 4) = l1;
            } else {
                float4 v = *(const float4*)&W[(size_t)(colBase + r) * EE + k0g + c4];
                uint32_t h0, l0, h1, l1;
                f32x2_hilo(v.x, v.y, h0, l0);
                f32x2_hilo(v.z, v.w, h1, l1);
                *(uint32_t*)(smem + OFF_BHI + so)     = h0;
                *(uint32_t*)(smem + OFF_BHI + so + 4) = h1;
                *(uint32_t*)(smem + OFF_BLO + so)     = l0;
                *(uint32_t*)(smem + OFF_BLO + so + 4) = l1;
            }
        }
        __syncthreads();

        // --- compute: 4 k-steps of 16 ---
#pragma unroll
        for (int ks = 0; ks < 4; ks++) {
            const int k0 = ks * 16 + tig * 2;
            uint32_t ah[2][4], al[2][4];
#pragma unroll
            for (int mt = 0; mt < 2; mt++) {
                int r0 = warpM * 32 + mt * 16 + g;
                uint32_t o00 = (uint32_t)(r0 * TROWB + k0 * 2);
                uint32_t o10 = o00 + 8 * TROWB;
                ah[mt][0] = *(const uint32_t*)(smem + OFF_AHI + o00);
                ah[mt][1] = *(const uint32_t*)(smem + OFF_AHI + o10);
                ah[mt][2] = *(const uint32_t*)(smem + OFF_AHI + o00 + 16);
                ah[mt][3] = *(const uint32_t*)(smem + OFF_AHI + o10 + 16);
                al[mt][0] = *(const uint32_t*)(smem + OFF_ALO + o00);
                al[mt][1] = *(const uint32_t*)(smem + OFF_ALO + o10);
                al[mt][2] = *(const uint32_t*)(smem + OFF_ALO + o00 + 16);
                al[mt][3] = *(const uint32_t*)(smem + OFF_ALO + o10 + 16);
            }
#pragma unroll
            for (int nt = 0; nt < 8; nt++) {
                int c0 = warpN * 64 + nt * 8 + g;
                uint32_t ob = (uint32_t)(c0 * TROWB + k0 * 2);
                uint32_t bh0 = *(const uint32_t*)(smem + OFF_BHI + ob);
                uint32_t bh1 = *(const uint32_t*)(smem + OFF_BHI + ob + 16);
                uint32_t bl0 = *(const uint32_t*)(smem + OFF_BLO + ob);
                uint32_t bl1 = *(const uint32_t*)(smem + OFF_BLO + ob + 16);
#pragma unroll
                for (int mt = 0; mt < 2; mt++) {
                    mma_bf16(acc[mt][nt], ah[mt][0], ah[mt][1], ah[mt][2], ah[mt][3], bh0, bh1);
                    mma_bf16(acc[mt][nt], ah[mt][0], ah[mt][1], ah[mt][2], ah[mt][3], bl0, bl1);
                    mma_bf16(acc[mt][nt], al[mt][0], al[mt][1], al[mt][2], al[mt][3], bh0, bh1);
                }
            }
        }
        __syncthreads();
    }

    // --- epilogue: + bias, write fp32 ---
#pragma unroll
    for (int nt = 0; nt < 8; nt++) {
        int col = colBase + warpN * 64 + nt * 8 + tig * 2;
        float b0 = bias[col], b1 = bias[col + 1];
#pragma unroll
        for (int mt = 0; mt < 2; mt++) {
            int row0 = rowBase + warpM * 32 + mt * 16 + g;
            float2 v0 = make_float2(acc[mt][nt][0] + b0, acc[mt][nt][1] + b1);
            float2 v1 = make_float2(acc[mt][nt][2] + b0, acc[mt][nt][3] + b1);
            *(float2*)&C[(size_t)row0 * EE + col]       = v0;
            *(float2*)&C[(size_t)(row0 + 8) * EE + col] = v1;
        }
    }
}

// ===========================================================================
// scores + online row stats (fp32, unchanged from R4 pass @975us)
// ===========================================================================
__global__ __launch_bounds__(256) void scores_stats_kernel(float* __restrict__ attn)
{
    const int bh = blockIdx.y;
    const int b  = bh >> 4;
    const int h  = bh & 15;
    const int rowBase = blockIdx.x * 128;
    const float* __restrict__ Qp = g_q + (size_t)b * SS * EE + h * DD;
    const float* __restrict__ Kp = g_k + (size_t)b * SS * EE + h * DD;
    float* __restrict__ Cb = attn + (size_t)bh * SS * SS;

    __shared__ __align__(16) float Qs[64][128];
    __shared__ __align__(16) float Ks[16][128];

    const int tid = threadIdx.x;
    const int ty = tid >> 4;
    const int tx = tid & 15;

#pragma unroll
    for (int l = 0; l < 8; l++) {
        int id = tid + l * 256;
        int r  = id >> 4;
        int c4 = (id & 15) << 2;
        float4 qv = *(const float4*)&Qp[(size_t)(rowBase + r) * EE + c4];
        Qs[c4 + 0][r] = qv.x; Qs[c4 + 1][r] = qv.y;
        Qs[c4 + 2][r] = qv.z; Qs[c4 + 3][r] = qv.w;
    }

    float m_run[8], s_run[8];
#pragma unroll
    for (int i = 0; i < 8; i++) { m_run[i] = -INFINITY; s_run[i] = 0.f; }

    for (int ct = 0; ct < SS / 128; ct++) {
        const int colBase = ct * 128;
        float acc[8][8];
#pragma unroll
        for (int i = 0; i < 8; i++)
#pragma unroll
            for (int j = 0; j < 8; j++) acc[i][j] = 0.f;

#pragma unroll
        for (int kc = 0; kc < 4; kc++) {
            __syncthreads();
#pragma unroll
            for (int l = 0; l < 2; l++) {
                int id = tid + l * 256;
                int r  = id >> 2;
                int c4 = (id & 3) << 2;
                float4 kv = *(const float4*)&Kp[(size_t)(colBase + r) * EE + kc * 16 + c4];
                Ks[c4 + 0][r] = kv.x; Ks[c4 + 1][r] = kv.y;
                Ks[c4 + 2][r] = kv.z; Ks[c4 + 3][r] = kv.w;
            }
            __syncthreads();
#pragma unroll
            for (int kk = 0; kk < 16; kk++) {
                float4 a0 = *(const float4*)&Qs[kc * 16 + kk][ty * 8];
                float4 a1 = *(const float4*)&Qs[kc * 16 + kk][ty * 8 + 4];
                float4 b0 = *(const float4*)&Ks[kk][tx * 8];
                float4 b1 = *(const float4*)&Ks[kk][tx * 8 + 4];
                float a[8] = {a0.x, a0.y, a0.z, a0.w, a1.x, a1.y, a1.z, a1.w};
                float bv[8] = {b0.x, b0.y, b0.z, b0.w, b1.x, b1.y, b1.z, b1.w};
#pragma unroll
                for (int i = 0; i < 8; i++)
#pragma unroll
                    for (int j = 0; j < 8; j++) acc[i][j] += a[i] * bv[j];
            }
        }

#pragma unroll
        for (int i = 0; i < 8; i++) {
#pragma unroll
            for (int j = 0; j < 8; j++) acc[i][j] *= 0.125f;
            int row = rowBase + ty * 8 + i;
            float4 o0 = make_float4(acc[i][0], acc[i][1], acc[i][2], acc[i][3]);
            float4 o1 = make_float4(acc[i][4], acc[i][5], acc[i][6], acc[i][7]);
            *(float4*)&Cb[(size_t)row * SS + colBase + tx * 8]     = o0;
            *(float4*)&Cb[(size_t)row * SS + colBase + tx * 8 + 4] = o1;
        }

#pragma unroll
        for (int i = 0; i < 8; i++) {
            float rmax = acc[i][0];
#pragma unroll
            for (int j = 1; j < 8; j++) rmax = fmaxf(rmax, acc[i][j]);
#pragma unroll
            for (int off = 8; off > 0; off >>= 1)
                rmax = fmaxf(rmax, __shfl_xor_sync(0xffffffffu, rmax, off));
            float m_new = fmaxf(m_run[i], rmax);
            float psum = 0.f;
#pragma unroll
            for (int j = 0; j < 8; j++) psum += __expf(acc[i][j] - m_new);
#pragma unroll
            for (int off = 8; off > 0; off >>= 1)
                psum += __shfl_xor_sync(0xffffffffu, psum, off);
            s_run[i] = s_run[i] * __expf(m_run[i] - m_new) + psum;
            m_run[i] = m_new;
        }
    }

    if (tx == 0) {
#pragma unroll
        for (int i = 0; i < 8; i++) {
            int row = rowBase + ty * 8 + i;
            g_m[(size_t)bh * SS + row] = m_run[i];
            g_s[(size_t)bh * SS + row] = s_run[i];
        }
    }
}

// ===========================================================================
// normalize + PV + feature-dim softmax (fp32, unchanged)
// ===========================================================================
__global__ __launch_bounds__(256) void norm_pv_kernel(float* __restrict__ attn)
{
    const int bh = blockIdx.y;
    const int b  = bh >> 4;
    const int h  = bh & 15;
    const int rowBase = blockIdx.x * 128;
    float* __restrict__ P = attn + (size_t)bh * SS * SS;
    const float* __restrict__ V = g_v + (size_t)b * SS * EE + h * DD;

    __shared__ __align__(16) float Ps[16][128];
    __shared__ __align__(16) float Vs[16][64];
    __shared__ float Ct[128][65];
    __shared__ float m_s[128];
    __shared__ float i_s[128];

    const int tid = threadIdx.x;
    const int ty = tid >> 4;
    const int tx = tid & 15;

    if (tid < 128) {
        m_s[tid] = g_m[(size_t)bh * SS + rowBase + tid];
        i_s[tid] = 1.f / g_s[(size_t)bh * SS + rowBase + tid];
    }
    __syncthreads();

    float acc[8][4];
#pragma unroll
    for (int i = 0; i < 8; i++)
#pragma unroll
        for (int j = 0; j < 4; j++) acc[i][j] = 0.f;

    for (int k0 = 0; k0 < SS; k0 += 16) {
#pragma unroll
        for (int l = 0; l < 2; l++) {
            int id = tid + l * 256;
            int r  = id >> 2;
            int c4 = (id & 3) << 2;
            float* addr = &P[(size_t)(rowBase + r) * SS + k0 + c4];
            float4 pv = *(const float4*)addr;
            float m = m_s[r], inv = i_s[r];
            pv.x = __expf(pv.x - m) * inv;
            pv.y = __expf(pv.y - m) * inv;
            pv.z = __expf(pv.z - m) * inv;
            pv.w = __expf(pv.w - m) * inv;
            *(float4*)addr = pv;
            Ps[c4 + 0][r] = pv.x; Ps[c4 + 1][r] = pv.y;
            Ps[c4 + 2][r] = pv.z; Ps[c4 + 3][r] = pv.w;
        }
        {
            int r = tid >> 4;
            int c = (tid & 15) << 2;
            *(float4*)&Vs[r][c] = *(const float4*)&V[(size_t)(k0 + r) * EE + c];
        }
        __syncthreads();
#pragma unroll
        for (int kk = 0; kk < 16; kk++) {
            float4 a0 = *(const float4*)&Ps[kk][ty * 8];
            float4 a1 = *(const float4*)&Ps[kk][ty * 8 + 4];
            float4 b0 = *(const float4*)&Vs[kk][tx * 4];
            float a[8] = {a0.x, a0.y, a0.z, a0.w, a1.x, a1.y, a1.z, a1.w};
            float bv[4] = {b0.x, b0.y, b0.z, b0.w};
#pragma unroll
            for (int i = 0; i < 8; i++)
#pragma unroll
                for (int j = 0; j < 4; j++) acc[i][j] += a[i] * bv[j];
        }
        __syncthreads();
    }

#pragma unroll
    for (int i = 0; i < 8; i++)
#pragma unroll
        for (int j = 0; j < 4; j++) Ct[ty * 8 + i][tx * 4 + j] = acc[i][j];
    __syncthreads();

    if (tid < 128) {
        const int r = tid;
        float m = Ct[r][0];
#pragma unroll
        for (int d = 1; d < DD; d++) m = fmaxf(m, Ct[r][d]);
        float s = 0.f;
#pragma unroll
        for (int d = 0; d < DD; d++) { float e = __expf(Ct[r][d] - m); Ct[r][d] = e; s += e; }
        float inv = 1.f / s;
        float* __restrict__ dst = g_ctx + ((size_t)b * SS + rowBase + r) * EE + h * DD;
#pragma unroll
        for (int d = 0; d < DD; d++) dst[d] = Ct[r][d] * inv;
    }
}

// ---------------------------------------------------------------------------
extern "C" void kernel_launch(void* const* d_in, const int* in_sizes, int n_in,
                              void* d_out, int out_size)
{
    const float* key   = (const float*)d_in[0];
    const float* query = (const float*)d_in[1];
    const float* value = (const float*)d_in[2];
    const float* wk_w  = (const float*)d_in[3];
    const float* wk_b  = (const float*)d_in[4];
    const float* wq_w  = (const float*)d_in[5];
    const float* wq_b  = (const float*)d_in[6];
    const float* wv_w  = (const float*)d_in[7];
    const float* wv_b  = (const float*)d_in[8];
    const float* out_w = (const float*)d_in[9];
    const float* out_b = (const float*)d_in[10];

    float* out  = (float*)d_out;                       // [B,S,E]
    float* attn = out + (size_t)MTOT * EE;             // [B,H,S,S]

    static int smem_set = 0;
    if (!smem_set) {
        cudaFuncSetAttribute(gemm_mma_kernel,
                             cudaFuncAttributeMaxDynamicSharedMemorySize, GEMM_SMEM);
        smem_set = 1;
    }

    dim3 gProj(EE / 128, MTOT / 128);                  // (8, 64)
    gemm_mma_kernel<<<gProj, 256, GEMM_SMEM>>>(query, 0, wq_w, wq_b, nullptr, 0);
    gemm_mma_kernel<<<gProj, 256, GEMM_SMEM>>>(key,   0, wk_w, wk_b, nullptr, 1);
    gemm_mma_kernel<<<gProj, 256, GEMM_SMEM>>>(value, 0, wv_w, wv_b, nullptr, 2);

    dim3 gScores(SS / 128, BH);                        // (16, 64)
    scores_stats_kernel<<<gScores, 256>>>(attn);

    dim3 gPV(SS / 128, BH);                            // (16, 64)
    norm_pv_kernel<<<gPV, 256>>>(attn);

    gemm_mma_kernel<<<gProj, 256, GEMM_SMEM>>>(nullptr, 1, out_w, out_b, out, 3);
}

// round 7
// speedup vs baseline: 1.5150x; 1.1374x over previous
#include <cuda_runtime.h>
#include <cuda_bf16.h>
#include <math.h>
#include <stdint.h>

// MultiHeadAttention: B=4, S=2048, E=1024, H=16, D=64
// Outputs: out [B,S,E] fp32, attention_weights [B,H,S,S] fp32.
//
// R7: scores kernel converted to mma.sync bf16 3-term split (same validated
// fragment layout as the projection GEMM). Projections (R6) and norm_pv (R3)
// unchanged.

#define BB   4
#define SS   2048
#define EE   1024
#define HH   16
#define DD   64
#define MTOT (BB*SS)          // 8192
#define BH   (BB*HH)          // 64

__device__ float g_q[MTOT*EE];
__device__ float g_k[MTOT*EE];
__device__ float g_v[MTOT*EE];
__device__ float g_ctx[MTOT*EE];
__device__ float g_m[BH*SS];
__device__ float g_s[BH*SS];

// ===========================================================================
// bf16 hi/lo split helpers + warp mma
// ===========================================================================
__device__ __forceinline__ void f32x2_hilo(float x, float y, uint32_t& hi, uint32_t& lo) {
    __nv_bfloat162 h, l;
    h.x = __float2bfloat16(x); l.x = __float2bfloat16(x - __bfloat162float(h.x));
    h.y = __float2bfloat16(y); l.y = __float2bfloat16(y - __bfloat162float(h.y));
    hi = *(uint32_t*)&h; lo = *(uint32_t*)&l;
}

__device__ __forceinline__ void mma_bf16(float* d,
    uint32_t a0, uint32_t a1, uint32_t a2, uint32_t a3, uint32_t b0, uint32_t b1)
{
    asm volatile(
        "mma.sync.aligned.m16n8k16.row.col.f32.bf16.bf16.f32 "
        "{%0,%1,%2,%3}, {%4,%5,%6,%7}, {%8,%9}, {%0,%1,%2,%3};"
        : "+f"(d[0]), "+f"(d[1]), "+f"(d[2]), "+f"(d[3])
        : "r"(a0), "r"(a1), "r"(a2), "r"(a3), "r"(b0), "r"(b1));
}

#define TPAD   72                       // bf16 elems per smem row (64 + 8 pad)
#define TROWB  (TPAD*2)                 // 144 bytes

// ===========================================================================
// Tensor-core projection GEMM (unchanged from R6 pass): C = A @ W^T + bias.
// ===========================================================================
#define OFF_AHI 0
#define OFF_ALO (128*TROWB)             // 18432
#define OFF_BHI (2*128*TROWB)           // 36864
#define OFF_BLO (3*128*TROWB)           // 55296
#define GEMM_SMEM (4*128*TROWB)         // 73728

__global__ __launch_bounds__(256, 1) void gemm_mma_kernel(
    const float* __restrict__ A_ext, int a_sel,
    const float* __restrict__ W, const float* __restrict__ bias,
    float* __restrict__ C_ext, int c_sel)
{
    extern __shared__ __align__(16) char smem[];

    const float* __restrict__ A = (a_sel == 0) ? A_ext : g_ctx;
    float* __restrict__ C;
    switch (c_sel) {
        case 0:  C = g_q;   break;
        case 1:  C = g_k;   break;
        case 2:  C = g_v;   break;
        default: C = C_ext; break;
    }

    const int tid  = threadIdx.x;
    const int wid  = tid >> 5;
    const int lane = tid & 31;
    const int g    = lane >> 2;
    const int tig  = lane & 3;
    const int warpM = wid & 3;
    const int warpN = wid >> 2;
    const int rowBase = blockIdx.y * 128;
    const int colBase = blockIdx.x * 128;

    float acc[2][8][4];
#pragma unroll
    for (int mt = 0; mt < 2; mt++)
#pragma unroll
        for (int nt = 0; nt < 8; nt++)
#pragma unroll
            for (int f = 0; f < 4; f++) acc[mt][nt][f] = 0.f;

    for (int kc = 0; kc < 16; kc++) {
        const int k0g = kc * 64;
#pragma unroll
        for (int l = 0; l < 16; l++) {
            int id   = tid + l * 256;
            int slot = id & 2047;
            int r    = slot >> 4;
            int c4   = (slot & 15) << 2;
            uint32_t so = (uint32_t)(r * TROWB + c4 * 2);
            if (id < 2048) {
                float4 v = *(const float4*)&A[(size_t)(rowBase + r) * EE + k0g + c4];
                uint32_t h0, l0, h1, l1;
                f32x2_hilo(v.x, v.y, h0, l0);
                f32x2_hilo(v.z, v.w, h1, l1);
                *(uint32_t*)(smem + OFF_AHI + so)     = h0;
                *(uint32_t*)(smem + OFF_AHI + so + 4) = h1;
                *(uint32_t*)(smem + OFF_ALO + so)     = l0;
                *(uint32_t*)(smem + OFF_ALO + so + 4) = l1;
            } else {
                float4 v = *(const float4*)&W[(size_t)(colBase + r) * EE + k0g + c4];
                uint32_t h0, l0, h1, l1;
                f32x2_hilo(v.x, v.y, h0, l0);
                f32x2_hilo(v.z, v.w, h1, l1);
                *(uint32_t*)(smem + OFF_BHI + so)     = h0;
                *(uint32_t*)(smem + OFF_BHI + so + 4) = h1;
                *(uint32_t*)(smem + OFF_BLO + so)     = l0;
                *(uint32_t*)(smem + OFF_BLO + so + 4) = l1;
            }
        }
        __syncthreads();

#pragma unroll
        for (int ks = 0; ks < 4; ks++) {
            const int k0 = ks * 16 + tig * 2;
            uint32_t ah[2][4], al[2][4];
#pragma unroll
            for (int mt = 0; mt < 2; mt++) {
                int r0 = warpM * 32 + mt * 16 + g;
                uint32_t o00 = (uint32_t)(r0 * TROWB + k0 * 2);
                uint32_t o10 = o00 + 8 * TROWB;
                ah[mt][0] = *(const uint32_t*)(smem + OFF_AHI + o00);
                ah[mt][1] = *(const uint32_t*)(smem + OFF_AHI + o10);
                ah[mt][2] = *(const uint32_t*)(smem + OFF_AHI + o00 + 16);
                ah[mt][3] = *(const uint32_t*)(smem + OFF_AHI + o10 + 16);
                al[mt][0] = *(const uint32_t*)(smem + OFF_ALO + o00);
                al[mt][1] = *(const uint32_t*)(smem + OFF_ALO + o10);
                al[mt][2] = *(const uint32_t*)(smem + OFF_ALO + o00 + 16);
                al[mt][3] = *(const uint32_t*)(smem + OFF_ALO + o10 + 16);
            }
#pragma unroll
            for (int nt = 0; nt < 8; nt++) {
                int c0 = warpN * 64 + nt * 8 + g;
                uint32_t ob = (uint32_t)(c0 * TROWB + k0 * 2);
                uint32_t bh0 = *(const uint32_t*)(smem + OFF_BHI + ob);
                uint32_t bh1 = *(const uint32_t*)(smem + OFF_BHI + ob + 16);
                uint32_t bl0 = *(const uint32_t*)(smem + OFF_BLO + ob);
                uint32_t bl1 = *(const uint32_t*)(smem + OFF_BLO + ob + 16);
#pragma unroll
                for (int mt = 0; mt < 2; mt++) {
                    mma_bf16(acc[mt][nt], ah[mt][0], ah[mt][1], ah[mt][2], ah[mt][3], bh0, bh1);
                    mma_bf16(acc[mt][nt], ah[mt][0], ah[mt][1], ah[mt][2], ah[mt][3], bl0, bl1);
                    mma_bf16(acc[mt][nt], al[mt][0], al[mt][1], al[mt][2], al[mt][3], bh0, bh1);
                }
            }
        }
        __syncthreads();
    }

#pragma unroll
    for (int nt = 0; nt < 8; nt++) {
        int col = colBase + warpN * 64 + nt * 8 + tig * 2;
        float b0 = bias[col], b1 = bias[col + 1];
#pragma unroll
        for (int mt = 0; mt < 2; mt++) {
            int row0 = rowBase + warpM * 32 + mt * 16 + g;
            float2 v0 = make_float2(acc[mt][nt][0] + b0, acc[mt][nt][1] + b1);
            float2 v1 = make_float2(acc[mt][nt][2] + b0, acc[mt][nt][3] + b1);
            *(float2*)&C[(size_t)row0 * EE + col]       = v0;
            *(float2*)&C[(size_t)(row0 + 8) * EE + col] = v1;
        }
    }
}

// ===========================================================================
// R7: scores + online row stats via mma.sync bf16 3-term split.
// CTA = 128-query-row stripe of one (b,h), loops over 16 key tiles of 128.
// 8 warps = 4(M) x 2(N). Q staged hi/lo once; K tiles streamed.
// Each N-warp tracks (m,s) over its column half; halves merged at the end.
// Smem: Qhi/Qlo/Khi/Klo [128][72] bf16 = 73728 B dynamic + small static.
// ===========================================================================
#define SC_QHI 0
#define SC_QLO (128*TROWB)
#define SC_KHI (2*128*TROWB)
#define SC_KLO (3*128*TROWB)
#define SC_SMEM (4*128*TROWB)           // 73728

__global__ __launch_bounds__(256, 1) void scores_mma_kernel(float* __restrict__ attn)
{
    extern __shared__ __align__(16) char smem[];
    __shared__ float sm_m[2][128];
    __shared__ float sm_s[2][128];

    const int bh = blockIdx.y;
    const int b  = bh >> 4;
    const int h  = bh & 15;
    const int rowBase = blockIdx.x * 128;
    const float* __restrict__ Qp = g_q + (size_t)b * SS * EE + h * DD;
    const float* __restrict__ Kp = g_k + (size_t)b * SS * EE + h * DD;
    float* __restrict__ Cb = attn + (size_t)bh * SS * SS;

    const int tid  = threadIdx.x;
    const int wid  = tid >> 5;
    const int lane = tid & 31;
    const int g    = lane >> 2;          // 0..7
    const int tig  = lane & 3;           // 0..3
    const int warpM = wid & 3;
    const int warpN = wid >> 2;

    // --- stage Q tile (128 x 64) as bf16 hi/lo, once ---
#pragma unroll
    for (int l = 0; l < 8; l++) {
        int id = tid + l * 256;          // 0..2047
        int r  = id >> 4;                // 0..127
        int c4 = (id & 15) << 2;         // 0..60
        uint32_t so = (uint32_t)(r * TROWB + c4 * 2);
        float4 v = *(const float4*)&Qp[(size_t)(rowBase + r) * EE + c4];
        uint32_t h0, l0, h1, l1;
        f32x2_hilo(v.x, v.y, h0, l0);
        f32x2_hilo(v.z, v.w, h1, l1);
        *(uint32_t*)(smem + SC_QHI + so)     = h0;
        *(uint32_t*)(smem + SC_QHI + so + 4) = h1;
        *(uint32_t*)(smem + SC_QLO + so)     = l0;
        *(uint32_t*)(smem + SC_QLO + so + 4) = l1;
    }

    // running stats: thread owns rows {base, base+8} for mt=0,1
    // idx 2*mt + p  -> row = warpM*32 + mt*16 + p*8 + g
    float m_run[4], s_run[4];
#pragma unroll
    for (int i = 0; i < 4; i++) { m_run[i] = -INFINITY; s_run[i] = 0.f; }

    for (int ct = 0; ct < 16; ct++) {
        const int colBase = ct * 128;
        // --- stage K tile (128 cols x 64 d) as bf16 hi/lo ---
        __syncthreads();
#pragma unroll
        for (int l = 0; l < 8; l++) {
            int id = tid + l * 256;
            int r  = id >> 4;
            int c4 = (id & 15) << 2;
            uint32_t so = (uint32_t)(r * TROWB + c4 * 2);
            float4 v = *(const float4*)&Kp[(size_t)(colBase + r) * EE + c4];
            uint32_t h0, l0, h1, l1;
            f32x2_hilo(v.x, v.y, h0, l0);
            f32x2_hilo(v.z, v.w, h1, l1);
            *(uint32_t*)(smem + SC_KHI + so)     = h0;
            *(uint32_t*)(smem + SC_KHI + so + 4) = h1;
            *(uint32_t*)(smem + SC_KLO + so)     = l0;
            *(uint32_t*)(smem + SC_KLO + so + 4) = l1;
        }
        __syncthreads();

        float acc[2][8][4];
#pragma unroll
        for (int mt = 0; mt < 2; mt++)
#pragma unroll
            for (int nt = 0; nt < 8; nt++)
#pragma unroll
                for (int f = 0; f < 4; f++) acc[mt][nt][f] = 0.f;

#pragma unroll
        for (int ks = 0; ks < 4; ks++) {
            const int k0 = ks * 16 + tig * 2;
            uint32_t ah[2][4], al[2][4];
#pragma unroll
            for (int mt = 0; mt < 2; mt++) {
                int r0 = warpM * 32 + mt * 16 + g;
                uint32_t o00 = (uint32_t)(r0 * TROWB + k0 * 2);
                uint32_t o10 = o00 + 8 * TROWB;
                ah[mt][0] = *(const uint32_t*)(smem + SC_QHI + o00);
                ah[mt][1] = *(const uint32_t*)(smem + SC_QHI + o10);
                ah[mt][2] = *(const uint32_t*)(smem + SC_QHI + o00 + 16);
                ah[mt][3] = *(const uint32_t*)(smem + SC_QHI + o10 + 16);
                al[mt][0] = *(const uint32_t*)(smem + SC_QLO + o00);
                al[mt][1] = *(const uint32_t*)(smem + SC_QLO + o10);
                al[mt][2] = *(const uint32_t*)(smem + SC_QLO + o00 + 16);
                al[mt][3] = *(const uint32_t*)(smem + SC_QLO + o10 + 16);
            }
#pragma unroll
            for (int nt = 0; nt < 8; nt++) {
                int c0 = warpN * 64 + nt * 8 + g;
                uint32_t ob = (uint32_t)(c0 * TROWB + k0 * 2);
                uint32_t bh0 = *(const uint32_t*)(smem + SC_KHI + ob);
                uint32_t bh1 = *(const uint32_t*)(smem + SC_KHI + ob + 16);
                uint32_t bl0 = *(const uint32_t*)(smem + SC_KLO + ob);
                uint32_t bl1 = *(const uint32_t*)(smem + SC_KLO + ob + 16);
#pragma unroll
                for (int mt = 0; mt < 2; mt++) {
                    mma_bf16(acc[mt][nt], ah[mt][0], ah[mt][1], ah[mt][2], ah[mt][3], bh0, bh1);
                    mma_bf16(acc[mt][nt], ah[mt][0], ah[mt][1], ah[mt][2], ah[mt][3], bl0, bl1);
                    mma_bf16(acc[mt][nt], al[mt][0], al[mt][1], al[mt][2], al[mt][3], bh0, bh1);
                }
            }
        }

        // --- scale, write raw scores, update per-half online stats ---
#pragma unroll
        for (int mt = 0; mt < 2; mt++) {
#pragma unroll
            for (int nt = 0; nt < 8; nt++) {
#pragma unroll
                for (int f = 0; f < 4; f++) acc[mt][nt][f] *= 0.125f;
                int col  = colBase + warpN * 64 + nt * 8 + tig * 2;
                int row0 = rowBase + warpM * 32 + mt * 16 + g;
                *(float2*)&Cb[(size_t)row0 * SS + col] =
                    make_float2(acc[mt][nt][0], acc[mt][nt][1]);
                *(float2*)&Cb[(size_t)(row0 + 8) * SS + col] =
                    make_float2(acc[mt][nt][2], acc[mt][nt][3]);
            }
#pragma unroll
            for (int p = 0; p < 2; p++) {
                int si = mt * 2 + p;
                float rmax = -INFINITY;
#pragma unroll
                for (int nt = 0; nt < 8; nt++) {
                    rmax = fmaxf(rmax, fmaxf(acc[mt][nt][p * 2], acc[mt][nt][p * 2 + 1]));
                }
                // reduce over the 4 tig lanes (consecutive: g*4 + tig)
                rmax = fmaxf(rmax, __shfl_xor_sync(0xffffffffu, rmax, 1));
                rmax = fmaxf(rmax, __shfl_xor_sync(0xffffffffu, rmax, 2));
                float m_new = fmaxf(m_run[si], rmax);
                float psum = 0.f;
#pragma unroll
                for (int nt = 0; nt < 8; nt++) {
                    psum += __expf(acc[mt][nt][p * 2]     - m_new);
                    psum += __expf(acc[mt][nt][p * 2 + 1] - m_new);
                }
                psum += __shfl_xor_sync(0xffffffffu, psum, 1);
                psum += __shfl_xor_sync(0xffffffffu, psum, 2);
                s_run[si] = s_run[si] * __expf(m_run[si] - m_new) + psum;
                m_run[si] = m_new;
            }
        }
    }

    // --- merge the two N-warp halves ---
    if (tig == 0) {
#pragma unroll
        for (int mt = 0; mt < 2; mt++)
#pragma unroll
            for (int p = 0; p < 2; p++) {
                int r = warpM * 32 + mt * 16 + p * 8 + g;
                sm_m[warpN][r] = m_run[mt * 2 + p];
                sm_s[warpN][r] = s_run[mt * 2 + p];
            }
    }
    __syncthreads();
    if (tid < 128) {
        float m0 = sm_m[0][tid], m1 = sm_m[1][tid];
        float mm = fmaxf(m0, m1);
        float ss = sm_s[0][tid] * __expf(m0 - mm) + sm_s[1][tid] * __expf(m1 - mm);
        g_m[(size_t)bh * SS + rowBase + tid] = mm;
        g_s[(size_t)bh * SS + rowBase + tid] = ss;
    }
}

// ===========================================================================
// normalize + PV + feature-dim softmax (fp32, unchanged)
// ===========================================================================
__global__ __launch_bounds__(256) void norm_pv_kernel(float* __restrict__ attn)
{
    const int bh = blockIdx.y;
    const int b  = bh >> 4;
    const int h  = bh & 15;
    const int rowBase = blockIdx.x * 128;
    float* __restrict__ P = attn + (size_t)bh * SS * SS;
    const float* __restrict__ V = g_v + (size_t)b * SS * EE + h * DD;

    __shared__ __align__(16) float Ps[16][128];
    __shared__ __align__(16) float Vs[16][64];
    __shared__ float Ct[128][65];
    __shared__ float m_s[128];
    __shared__ float i_s[128];

    const int tid = threadIdx.x;
    const int ty = tid >> 4;
    const int tx = tid & 15;

    if (tid < 128) {
        m_s[tid] = g_m[(size_t)bh * SS + rowBase + tid];
        i_s[tid] = 1.f / g_s[(size_t)bh * SS + rowBase + tid];
    }
    __syncthreads();

    float acc[8][4];
#pragma unroll
    for (int i = 0; i < 8; i++)
#pragma unroll
        for (int j = 0; j < 4; j++) acc[i][j] = 0.f;

    for (int k0 = 0; k0 < SS; k0 += 16) {
#pragma unroll
        for (int l = 0; l < 2; l++) {
            int id = tid + l * 256;
            int r  = id >> 2;
            int c4 = (id & 3) << 2;
            float* addr = &P[(size_t)(rowBase + r) * SS + k0 + c4];
            float4 pv = *(const float4*)addr;
            float m = m_s[r], inv = i_s[r];
            pv.x = __expf(pv.x - m) * inv;
            pv.y = __expf(pv.y - m) * inv;
            pv.z = __expf(pv.z - m) * inv;
            pv.w = __expf(pv.w - m) * inv;
            *(float4*)addr = pv;
            Ps[c4 + 0][r] = pv.x; Ps[c4 + 1][r] = pv.y;
            Ps[c4 + 2][r] = pv.z; Ps[c4 + 3][r] = pv.w;
        }
        {
            int r = tid >> 4;
            int c = (tid & 15) << 2;
            *(float4*)&Vs[r][c] = *(const float4*)&V[(size_t)(k0 + r) * EE + c];
        }
        __syncthreads();
#pragma unroll
        for (int kk = 0; kk < 16; kk++) {
            float4 a0 = *(const float4*)&Ps[kk][ty * 8];
            float4 a1 = *(const float4*)&Ps[kk][ty * 8 + 4];
            float4 b0 = *(const float4*)&Vs[kk][tx * 4];
            float a[8] = {a0.x, a0.y, a0.z, a0.w, a1.x, a1.y, a1.z, a1.w};
            float bv[4] = {b0.x, b0.y, b0.z, b0.w};
#pragma unroll
            for (int i = 0; i < 8; i++)
#pragma unroll
                for (int j = 0; j < 4; j++) acc[i][j] += a[i] * bv[j];
        }
        __syncthreads();
    }

#pragma unroll
    for (int i = 0; i < 8; i++)
#pragma unroll
        for (int j = 0; j < 4; j++) Ct[ty * 8 + i][tx * 4 + j] = acc[i][j];
    __syncthreads();

    if (tid < 128) {
        const int r = tid;
        float m = Ct[r][0];
#pragma unroll
        for (int d = 1; d < DD; d++) m = fmaxf(m, Ct[r][d]);
        float s = 0.f;
#pragma unroll
        for (int d = 0; d < DD; d++) { float e = __expf(Ct[r][d] - m); Ct[r][d] = e; s += e; }
        float inv = 1.f / s;
        float* __restrict__ dst = g_ctx + ((size_t)b * SS + rowBase + r) * EE + h * DD;
#pragma unroll
        for (int d = 0; d < DD; d++) dst[d] = Ct[r][d] * inv;
    }
}

// ---------------------------------------------------------------------------
extern "C" void kernel_launch(void* const* d_in, const int* in_sizes, int n_in,
                              void* d_out, int out_size)
{
    const float* key   = (const float*)d_in[0];
    const float* query = (const float*)d_in[1];
    const float* value = (const float*)d_in[2];
    const float* wk_w  = (const float*)d_in[3];
    const float* wk_b  = (const float*)d_in[4];
    const float* wq_w  = (const float*)d_in[5];
    const float* wq_b  = (const float*)d_in[6];
    const float* wv_w  = (const float*)d_in[7];
    const float* wv_b  = (const float*)d_in[8];
    const float* out_w = (const float*)d_in[9];
    const float* out_b = (const float*)d_in[10];

    float* out  = (float*)d_out;                       // [B,S,E]
    float* attn = out + (size_t)MTOT * EE;             // [B,H,S,S]

    static int smem_set = 0;
    if (!smem_set) {
        cudaFuncSetAttribute(gemm_mma_kernel,
                             cudaFuncAttributeMaxDynamicSharedMemorySize, GEMM_SMEM);
        cudaFuncSetAttribute(scores_mma_kernel,
                             cudaFuncAttributeMaxDynamicSharedMemorySize, SC_SMEM);
        smem_set = 1;
    }

    dim3 gProj(EE / 128, MTOT / 128);                  // (8, 64)
    gemm_mma_kernel<<<gProj, 256, GEMM_SMEM>>>(query, 0, wq_w, wq_b, nullptr, 0);
    gemm_mma_kernel<<<gProj, 256, GEMM_SMEM>>>(key,   0, wk_w, wk_b, nullptr, 1);
    gemm_mma_kernel<<<gProj, 256, GEMM_SMEM>>>(value, 0, wv_w, wv_b, nullptr, 2);

    dim3 gScores(SS / 128, BH);                        // (16, 64)
    scores_mma_kernel<<<gScores, 256, SC_SMEM>>>(attn);

    dim3 gPV(SS / 128, BH);                            // (16, 64)
    norm_pv_kernel<<<gPV, 256>>>(attn);

    gemm_mma_kernel<<<gProj, 256, GEMM_SMEM>>>(nullptr, 1, out_w, out_b, out, 3);
}